// round 7
// baseline (speedup 1.0000x reference)
#include <cuda_runtime.h>

#define E    4096
#define NVAR 1024
#define NCHK 512
#define EPS32   1.1920929e-07f
#define LN2F    0.6931471805599453f

// Upper-triangle peers of each edge (columns > row), ascending. Rows with
// cntA+cntB==7 (check representatives) have complete sorted lists; only those
// are ever read by decode.
__device__ int g_up[E * 7];
__device__ __align__(16) int g_cntA[E];
__device__ __align__(16) int g_cntB[E];

// ---------------- kernel A: upper-triangle scan, fixed trip count ------------
// w_odd_to_even is symmetric, zero diagonal, 7 nonzeros per row. 4096 warps:
// warp (p, sub) covers half of row p's upper suffix and half of row 4095-p's
// (per-warp work ~8KB, perfectly balanced, single wave). sub==0 compacts its
// finds ascending from dst[0]; sub==1 iterates its half from the END and
// compacts descending from dst[6]. For rep rows (7 total) the halves meet to
// form a full ascending list. COMPILE-TIME trip count (17) + predicated loads
// so ptxas batches LDG.128s (the round-5/6 variable-bounds loop killed MLP).
__global__ void build_peers_kernel(const float4* __restrict__ w) {
    int gw   = (blockIdx.x * blockDim.x + threadIdx.x) >> 5;   // 0..4095
    int lane = threadIdx.x & 31;
    int p    = gw >> 1;
    int sub  = gw & 1;
    const float4 z4 = make_float4(0.f, 0.f, 0.f, 0.f);
#pragma unroll
    for (int pass = 0; pass < 2; pass++) {
        int row = pass ? (E - 1 - p) : p;
        const float4* r = w + (size_t)row * (E / 4);
        int* dst = g_up + row * 7;
        int f0    = (row + 1) >> 2;        // first float4 containing a col > row
        int halfn = (1024 - f0) >> 1;
        int base  = 0;
        if (sub == 0) {
            int fend = f0 + halfn;         // ascending over [f0, fend)
#pragma unroll 4
            for (int i = 0; i < 17; i++) {
                int f = f0 + i * 32 + lane;
                float4 v = (f < fend) ? r[f] : z4;
                int col = f * 4;
                int c0 = (v.x != 0.f) & (col     > row);
                int c1 = (v.y != 0.f) & (col + 1 > row);
                int c2 = (v.z != 0.f) & (col + 2 > row);
                int c3 = (v.w != 0.f) & (col + 3 > row);
                int cnt = c0 + c1 + c2 + c3;
                unsigned b0 = __ballot_sync(0xffffffffu, cnt & 1);
                unsigned b1 = __ballot_sync(0xffffffffu, cnt & 2);
                unsigned b2 = __ballot_sync(0xffffffffu, cnt & 4);
                if (b0 | b1 | b2) {        // warp-uniform, rare
                    unsigned lo = (1u << lane) - 1u;
                    int idx = base + __popc(b0 & lo) + 2 * __popc(b1 & lo)
                                   + 4 * __popc(b2 & lo);
                    if (c0) dst[idx++] = col;
                    if (c1) dst[idx++] = col + 1;
                    if (c2) dst[idx++] = col + 2;
                    if (c3) dst[idx]   = col + 3;
                    base += __popc(b0) + 2 * __popc(b1) + 4 * __popc(b2);
                }
            }
            if (lane == 0) g_cntA[row] = base;
        } else {
            int fbeg = f0 + halfn;         // descending over [fbeg, 1024)
#pragma unroll 4
            for (int i = 0; i < 17; i++) {
                int f = 1024 - (i + 1) * 32 + lane;   // chunks from the end
                float4 v = (f >= fbeg) ? r[f] : z4;
                int col = f * 4;
                int c0 = (v.x != 0.f) & (col     > row);
                int c1 = (v.y != 0.f) & (col + 1 > row);
                int c2 = (v.z != 0.f) & (col + 2 > row);
                int c3 = (v.w != 0.f) & (col + 3 > row);
                int cnt = c0 + c1 + c2 + c3;
                unsigned b0 = __ballot_sync(0xffffffffu, cnt & 1);
                unsigned b1 = __ballot_sync(0xffffffffu, cnt & 2);
                unsigned b2 = __ballot_sync(0xffffffffu, cnt & 4);
                if (b0 | b1 | b2) {
                    unsigned hi = (lane == 31) ? 0u : (0xffffffffu << (lane + 1));
                    int idx = base + __popc(b0 & hi) + 2 * __popc(b1 & hi)
                                   + 4 * __popc(b2 & hi);
                    // descending within my float4: highest col first
                    if (c3) { dst[6 - idx] = col + 3; idx++; }
                    if (c2) { dst[6 - idx] = col + 2; idx++; }
                    if (c1) { dst[6 - idx] = col + 1; idx++; }
                    if (c0) { dst[6 - idx] = col;            }
                    base += __popc(b0) + 2 * __popc(b1) + 4 * __popc(b2);
                }
            }
            if (lane == 0) g_cntB[row] = base;
        }
    }
}

// ---------------- math helpers -----------------------------------------------
__device__ __forceinline__ float tanh_acc(float a) {
    // tanh(a) = 1 - 2/(exp(2a)+1); inf-safe (saturates to +-1 exactly)
    return 1.0f - __fdividef(2.0f, __expf(2.0f * a) + 1.0f);
}

__device__ __forceinline__ float atanh2(float v) {
    // reference clamps: v>=1 -> 1-eps, v<=-1 -> -1+eps (exact copy)
    v = (v >= 1.0f) ? (1.0f - EPS32) : v;
    v = (v <= -1.0f) ? (-1.0f + EPS32) : v;
    // 2*atanh(v) = ln2*(lg2(1+v) - lg2(1-v)); two independent MUFU lg2
    return LN2F * (__log2f(1.0f + v) - __log2f(1.0f - v));
}

__device__ __forceinline__ float zsub(float o) {
    return (o == 0.0f) ? 1.0f : o;   // reference maps exact zeros -> identity
}

// ---------------- kernel B: full decode, one persistent block ----------------
__global__ __launch_bounds__(1024, 1)
void decode_kernel(const float* __restrict__ x, float* __restrict__ out) {
    __shared__ float sh_odd[E];      // odd messages, natural edge order
    __shared__ float sh_even[E];     // even messages, natural edge order
    __shared__ int   chk_list[NCHK]; // representative (min) edge per check
    __shared__ int   chk_ctr;

    const int t = threadIdx.x;
    const float llr = x[t];

    if (t == 0) chk_ctr = 0;
    ((float4*)sh_even)[t] = make_float4(0.f, 0.f, 0.f, 0.f);
    __syncthreads();

    // claim checks: edge e is representative iff all 7 peers are above it
    int4 ca = ((const int4*)g_cntA)[t];
    int4 cb = ((const int4*)g_cntB)[t];
    if (ca.x + cb.x == 7) chk_list[atomicAdd(&chk_ctr, 1)] = 4 * t;
    if (ca.y + cb.y == 7) chk_list[atomicAdd(&chk_ctr, 1)] = 4 * t + 1;
    if (ca.z + cb.z == 7) chk_list[atomicAdd(&chk_ctr, 1)] = 4 * t + 2;
    if (ca.w + cb.w == 7) chk_list[atomicAdd(&chk_ctr, 1)] = 4 * t + 3;
    __syncthreads();

    // check owners cache their sorted 8-edge list in registers (rep = minimum)
    int id0 = 0, id1 = 0, id2 = 0, id3 = 0, id4 = 0, id5 = 0, id6 = 0, id7 = 0;
    if (t < NCHK) {
        int rep = chk_list[t];
        const int* pp = g_up + rep * 7;
        id0 = rep;
        id1 = pp[0]; id2 = pp[1]; id3 = pp[2]; id4 = pp[3];
        id5 = pp[4]; id6 = pp[5]; id7 = pp[6];
    }

    // ---- 5 BP iterations ------------------------------------------------------
#pragma unroll 1
    for (int it = 0; it < 5; it++) {
        // odd stage: vectorized, natural order (thread t = variable t)
        float4 ev = ((float4*)sh_even)[t];
        float vs = ev.x + ev.y + ev.z + ev.w;
        float4 od;
        od.x = tanh_acc(0.5f * (llr + vs - ev.x));
        od.y = tanh_acc(0.5f * (llr + vs - ev.y));
        od.z = tanh_acc(0.5f * (llr + vs - ev.z));
        od.w = tanh_acc(0.5f * (llr + vs - ev.w));
        ((float4*)sh_odd)[t] = od;
        __syncthreads();

        // even stage: 512 check owners gather 8, extrinsic products, scatter 8
        if (t < NCHK) {
            float a0 = zsub(sh_odd[id0]), a1 = zsub(sh_odd[id1]);
            float a2 = zsub(sh_odd[id2]), a3 = zsub(sh_odd[id3]);
            float a4 = zsub(sh_odd[id4]), a5 = zsub(sh_odd[id5]);
            float a6 = zsub(sh_odd[id6]), a7 = zsub(sh_odd[id7]);
            float p01 = a0 * a1, p23 = a2 * a3, p45 = a4 * a5, p67 = a6 * a7;
            float q03 = p01 * p23, q47 = p45 * p67;
            sh_even[id0] = atanh2(a1 * p23 * q47);
            sh_even[id1] = atanh2(a0 * p23 * q47);
            sh_even[id2] = atanh2(p01 * a3 * q47);
            sh_even[id3] = atanh2(p01 * a2 * q47);
            sh_even[id4] = atanh2(q03 * a5 * p67);
            sh_even[id5] = atanh2(q03 * a4 * p67);
            sh_even[id6] = atanh2(q03 * p45 * a7);
            sh_even[id7] = atanh2(q03 * p45 * a6);
        }
        __syncthreads();
    }

    // ---- epilogue: out[n] = sigmoid(x[n] + sum of even over var n) ------------
    float4 ev = ((float4*)sh_even)[t];
    float z = llr + ev.x + ev.y + ev.z + ev.w;
    out[t] = __fdividef(1.0f, 1.0f + __expf(-z));
}

// ---------------- launch ------------------------------------------------------
extern "C" void kernel_launch(void* const* d_in, const int* in_sizes, int n_in,
                              void* d_out, int out_size) {
    (void)in_sizes; (void)n_in; (void)out_size;
    const float*  x = (const float*)d_in[0];
    const float4* w = (const float4*)d_in[2];   // w_odd_to_even [E,E]
    float* out = (float*)d_out;

    build_peers_kernel<<<512, 256>>>(w);   // 4096 warps, balanced halves
    decode_kernel<<<1, 1024>>>(x, out);
}

// round 8
// speedup vs baseline: 1.0371x; 1.0371x over previous
#include <cuda_runtime.h>

#define E    4096
#define NVAR 1024
#define NCHK 512
#define EPS32   1.1920929e-07f
#define LN2F    0.6931471805599453f

// Upper-triangle peers of each edge (columns > row), ascending. Rows with
// g_ucnt==7 (check representatives) have complete sorted lists; only those
// are ever read by decode. (An edge has exactly 7 peers; it is the check's
// minimum edge iff all 7 lie above it.)
__device__ int g_up[E * 7];
__device__ __align__(16) int g_ucnt[E];

// ---------------- kernel A: paired-row upper-triangle scan -------------------
// w_odd_to_even is symmetric, zero diagonal, 7 nonzeros/row. Warp gw covers
// rows rA=gw and rB=4095-gw. At 128-col chunk granularity the two upper-tri
// suffixes total 32 or 33 chunks, so a FIXED 33-iteration loop covers both
// with EVERY load unconditional, in-bounds and 512B-aligned (row/chunk picked
// by branchless selects). This replicates the round-3 load discipline that
// streamed at the LTS cap, on half the bytes. At most one wasted pre-diagonal
// chunk per row, neutralized by the col>row mask.
__global__ void build_peers_kernel(const float4* __restrict__ w) {
    int gw   = (blockIdx.x * blockDim.x + threadIdx.x) >> 5;   // 0..2047
    int lane = threadIdx.x & 31;
    int rA = gw, rB = (E - 1) - gw;
    int itersB  = 32 - ((E - rA) >> 7);       // chunks for row B: in [0,16]
    int itersAp = 33 - itersB;                // chunks for row A (incl. filler)
    int cA0 = itersB - 1;                     // row-A start chunk (may be -1)
    bool dupA = (cA0 < 0);                    // only when rA == 0
    const float4* rowA = w + (size_t)rA * (E / 4);
    const float4* rowB = w + (size_t)rB * (E / 4);
    int* dstA = g_up + rA * 7;
    int* dstB = g_up + rB * 7;
    int baseA = 0, baseB = 0;
#pragma unroll 4
    for (int k = 0; k < 33; k++) {
        bool isA   = (k < itersAp);
        int chunkA = (k == 0 && dupA) ? 0 : (cA0 + k);   // clamped corner
        int chunk  = isA ? chunkA : (k - 1);             // chunkB = k-1
        int row    = isA ? rA : rB;
        const float4* rp = isA ? rowA : rowB;
        float4 v = rp[chunk * 32 + lane];     // unconditional, aligned, in-bounds
        int col = chunk * 128 + lane * 4;
        int sup = (int)(dupA && k == 0);      // suppress the duplicated chunk
        int c0 = (v.x != 0.f) & (col     > row) & !sup;
        int c1 = (v.y != 0.f) & (col + 1 > row) & !sup;
        int c2 = (v.z != 0.f) & (col + 2 > row) & !sup;
        int c3 = (v.w != 0.f) & (col + 3 > row) & !sup;
        int cnt = c0 + c1 + c2 + c3;
        unsigned b0 = __ballot_sync(0xffffffffu, cnt & 1);
        unsigned b1 = __ballot_sync(0xffffffffu, cnt & 2);
        unsigned b2 = __ballot_sync(0xffffffffu, cnt & 4);
        if (b0 | b1 | b2) {                   // warp-uniform, rare
            unsigned lo = (1u << lane) - 1u;
            int prior = __popc(b0 & lo) + 2 * __popc(b1 & lo)
                      + 4 * __popc(b2 & lo);
            int idx = (isA ? baseA : baseB) + prior;
            int* dst = isA ? dstA : dstB;
            if (c0) dst[idx++] = col;
            if (c1) dst[idx++] = col + 1;
            if (c2) dst[idx++] = col + 2;
            if (c3) dst[idx]   = col + 3;
            int add = __popc(b0) + 2 * __popc(b1) + 4 * __popc(b2);
            if (isA) baseA += add; else baseB += add;
        }
    }
    if (lane == 0) { g_ucnt[rA] = baseA; g_ucnt[rB] = baseB; }
}

// ---------------- math helpers -----------------------------------------------
__device__ __forceinline__ float tanh_acc(float a) {
    // tanh(a) = 1 - 2/(exp(2a)+1); inf-safe (saturates to +-1 exactly)
    return 1.0f - __fdividef(2.0f, __expf(2.0f * a) + 1.0f);
}

__device__ __forceinline__ float atanh2(float v) {
    // reference clamps: v>=1 -> 1-eps, v<=-1 -> -1+eps (exact copy)
    v = (v >= 1.0f) ? (1.0f - EPS32) : v;
    v = (v <= -1.0f) ? (-1.0f + EPS32) : v;
    // 2*atanh(v) = ln2*(lg2(1+v) - lg2(1-v)); two independent MUFU lg2
    return LN2F * (__log2f(1.0f + v) - __log2f(1.0f - v));
}

__device__ __forceinline__ float zsub(float o) {
    return (o == 0.0f) ? 1.0f : o;   // reference maps exact zeros -> identity
}

// ---------------- kernel B: full decode, one persistent block ----------------
__global__ __launch_bounds__(1024, 1)
void decode_kernel(const float* __restrict__ x, float* __restrict__ out) {
    __shared__ float sh_odd[E];      // odd messages, natural edge order
    __shared__ float sh_even[E];     // even messages, natural edge order
    __shared__ int   chk_list[NCHK]; // representative (min) edge per check
    __shared__ int   chk_ctr;

    const int t = threadIdx.x;
    const float llr = x[t];

    if (t == 0) chk_ctr = 0;
    ((float4*)sh_even)[t] = make_float4(0.f, 0.f, 0.f, 0.f);
    __syncthreads();

    // claim checks: edge e is representative iff all 7 peers are above it
    int4 uc = ((const int4*)g_ucnt)[t];
    if (uc.x == 7) chk_list[atomicAdd(&chk_ctr, 1)] = 4 * t;
    if (uc.y == 7) chk_list[atomicAdd(&chk_ctr, 1)] = 4 * t + 1;
    if (uc.z == 7) chk_list[atomicAdd(&chk_ctr, 1)] = 4 * t + 2;
    if (uc.w == 7) chk_list[atomicAdd(&chk_ctr, 1)] = 4 * t + 3;
    __syncthreads();

    // check owners cache their sorted 8-edge list in registers (rep = minimum)
    int id0 = 0, id1 = 0, id2 = 0, id3 = 0, id4 = 0, id5 = 0, id6 = 0, id7 = 0;
    if (t < NCHK) {
        int rep = chk_list[t];
        const int* pp = g_up + rep * 7;
        id0 = rep;
        id1 = pp[0]; id2 = pp[1]; id3 = pp[2]; id4 = pp[3];
        id5 = pp[4]; id6 = pp[5]; id7 = pp[6];
    }

    // ---- 5 BP iterations ------------------------------------------------------
#pragma unroll 1
    for (int it = 0; it < 5; it++) {
        // odd stage: vectorized, natural order (thread t = variable t)
        float4 ev = ((float4*)sh_even)[t];
        float vs = ev.x + ev.y + ev.z + ev.w;
        float4 od;
        od.x = tanh_acc(0.5f * (llr + vs - ev.x));
        od.y = tanh_acc(0.5f * (llr + vs - ev.y));
        od.z = tanh_acc(0.5f * (llr + vs - ev.z));
        od.w = tanh_acc(0.5f * (llr + vs - ev.w));
        ((float4*)sh_odd)[t] = od;
        __syncthreads();

        // even stage: 512 check owners gather 8, extrinsic products, scatter 8
        if (t < NCHK) {
            float a0 = zsub(sh_odd[id0]), a1 = zsub(sh_odd[id1]);
            float a2 = zsub(sh_odd[id2]), a3 = zsub(sh_odd[id3]);
            float a4 = zsub(sh_odd[id4]), a5 = zsub(sh_odd[id5]);
            float a6 = zsub(sh_odd[id6]), a7 = zsub(sh_odd[id7]);
            float p01 = a0 * a1, p23 = a2 * a3, p45 = a4 * a5, p67 = a6 * a7;
            float q03 = p01 * p23, q47 = p45 * p67;
            sh_even[id0] = atanh2(a1 * p23 * q47);
            sh_even[id1] = atanh2(a0 * p23 * q47);
            sh_even[id2] = atanh2(p01 * a3 * q47);
            sh_even[id3] = atanh2(p01 * a2 * q47);
            sh_even[id4] = atanh2(q03 * a5 * p67);
            sh_even[id5] = atanh2(q03 * a4 * p67);
            sh_even[id6] = atanh2(q03 * p45 * a7);
            sh_even[id7] = atanh2(q03 * p45 * a6);
        }
        __syncthreads();
    }

    // ---- epilogue: out[n] = sigmoid(x[n] + sum of even over var n) ------------
    float4 ev = ((float4*)sh_even)[t];
    float z = llr + ev.x + ev.y + ev.z + ev.w;
    out[t] = __fdividef(1.0f, 1.0f + __expf(-z));
}

// ---------------- launch ------------------------------------------------------
extern "C" void kernel_launch(void* const* d_in, const int* in_sizes, int n_in,
                              void* d_out, int out_size) {
    (void)in_sizes; (void)n_in; (void)out_size;
    const float*  x = (const float*)d_in[0];
    const float4* w = (const float4*)d_in[2];   // w_odd_to_even [E,E]
    float* out = (float*)d_out;

    build_peers_kernel<<<256, 256>>>(w);   // 2048 warps, one row pair each
    decode_kernel<<<1, 1024>>>(x, out);
}

// round 9
// speedup vs baseline: 1.2736x; 1.2280x over previous
#include <cuda_runtime.h>

#define E    4096
#define NVAR 1024
#define NCHK 512
#define EPS32   1.1920929e-07f
#define LN2F    0.6931471805599453f

// Upper-triangle peers of each edge (columns > row), ascending. Rows with
// cntA+cntB==7 (check representatives) have complete sorted lists; only those
// are ever read by decode.
__device__ int g_up[E * 7];
__device__ __align__(16) int g_cntA[E];   // peers found in cols [0,2048)
__device__ __align__(16) int g_cntB[E];   // peers found in cols [2048,4096)

// ---------------- kernel A: half-row upper-triangle scan ---------------------
// 8192 warps, warp = (row, half). Each active warp does ONE fully-unrolled
// 16-chunk pass with every LDG.128 unconditional at an immediate offset (the
// round-3 load discipline that hit the BW roofline), on half a row. Half-0 is
// skipped outright (warp exit) when the whole half lies on/below the diagonal.
// Half-0 compacts finds ascending from dst[0]; half-1 walks its chunks in
// descending column order and compacts from dst[6] downward, so for rep rows
// (exactly 7 upper peers) the two fragments meet as one ascending list.
__global__ void build_peers_kernel(const float4* __restrict__ w) {
    int gw   = (blockIdx.x * blockDim.x + threadIdx.x) >> 5;   // 0..8191
    int lane = threadIdx.x & 31;
    int row  = gw >> 1;
    int h    = gw & 1;
    if (h == 0 && row >= 2047) return;     // half-0 entirely <= diagonal
    const float4* base = w + (size_t)row * (E / 4) + h * 512 + lane;
    int* dst = g_up + row * 7;
    int colb = h * 2048 + lane * 4;
    int total = 0;
    if (h == 0) {
#pragma unroll
        for (int i = 0; i < 16; i++) {
            float4 v = base[i * 32];                // unconditional, imm offset
            int col = colb + i * 128;
            int c0 = (v.x != 0.f) & (col     > row);
            int c1 = (v.y != 0.f) & (col + 1 > row);
            int c2 = (v.z != 0.f) & (col + 2 > row);
            int c3 = (v.w != 0.f) & (col + 3 > row);
            int cnt = c0 + c1 + c2 + c3;
            unsigned b0 = __ballot_sync(0xffffffffu, cnt & 1);
            unsigned b1 = __ballot_sync(0xffffffffu, cnt & 2);
            unsigned b2 = __ballot_sync(0xffffffffu, cnt & 4);
            if (b0 | b1 | b2) {                    // warp-uniform, rare
                unsigned lo = (1u << lane) - 1u;
                int idx = total + __popc(b0 & lo) + 2 * __popc(b1 & lo)
                                + 4 * __popc(b2 & lo);
                if (c0) dst[idx++] = col;
                if (c1) dst[idx++] = col + 1;
                if (c2) dst[idx++] = col + 2;
                if (c3) dst[idx]   = col + 3;
                total += __popc(b0) + 2 * __popc(b1) + 4 * __popc(b2);
            }
        }
        if (lane == 0) g_cntA[row] = total;
    } else {
#pragma unroll
        for (int i = 15; i >= 0; i--) {            // descending column order
            float4 v = base[i * 32];                // unconditional, imm offset
            int col = colb + i * 128;
            int c0 = (v.x != 0.f) & (col     > row);
            int c1 = (v.y != 0.f) & (col + 1 > row);
            int c2 = (v.z != 0.f) & (col + 2 > row);
            int c3 = (v.w != 0.f) & (col + 3 > row);
            int cnt = c0 + c1 + c2 + c3;
            unsigned b0 = __ballot_sync(0xffffffffu, cnt & 1);
            unsigned b1 = __ballot_sync(0xffffffffu, cnt & 2);
            unsigned b2 = __ballot_sync(0xffffffffu, cnt & 4);
            if (b0 | b1 | b2) {
                unsigned hi = (lane == 31) ? 0u : (0xffffffffu << (lane + 1));
                int idx = total + __popc(b0 & hi) + 2 * __popc(b1 & hi)
                                + 4 * __popc(b2 & hi);
                if (c3) { dst[6 - idx] = col + 3; idx++; }
                if (c2) { dst[6 - idx] = col + 2; idx++; }
                if (c1) { dst[6 - idx] = col + 1; idx++; }
                if (c0) { dst[6 - idx] = col;            }
                total += __popc(b0) + 2 * __popc(b1) + 4 * __popc(b2);
            }
        }
        if (lane == 0) g_cntB[row] = total;
    }
}

// ---------------- math helpers -----------------------------------------------
__device__ __forceinline__ float tanh_acc(float a) {
    // tanh(a) = 1 - 2/(exp(2a)+1); inf-safe (saturates to +-1 exactly)
    return 1.0f - __fdividef(2.0f, __expf(2.0f * a) + 1.0f);
}

__device__ __forceinline__ float atanh2(float v) {
    // reference clamps: v>=1 -> 1-eps, v<=-1 -> -1+eps (exact copy)
    v = (v >= 1.0f) ? (1.0f - EPS32) : v;
    v = (v <= -1.0f) ? (-1.0f + EPS32) : v;
    // 2*atanh(v) = ln2*(lg2(1+v) - lg2(1-v)); two independent MUFU lg2
    return LN2F * (__log2f(1.0f + v) - __log2f(1.0f - v));
}

__device__ __forceinline__ float zsub(float o) {
    return (o == 0.0f) ? 1.0f : o;   // reference maps exact zeros -> identity
}

// ---------------- kernel B: full decode, one persistent block ----------------
__global__ __launch_bounds__(1024, 1)
void decode_kernel(const float* __restrict__ x, float* __restrict__ out) {
    __shared__ float sh_odd[E];      // odd messages, natural edge order
    __shared__ float sh_even[E];     // even messages, natural edge order
    __shared__ int   chk_list[NCHK]; // representative (min) edge per check
    __shared__ int   chk_ctr;

    const int t = threadIdx.x;
    const float llr = x[t];

    if (t == 0) chk_ctr = 0;
    ((float4*)sh_even)[t] = make_float4(0.f, 0.f, 0.f, 0.f);
    __syncthreads();

    // claim checks: edge e is representative iff all 7 peers are above it
    int4 ca = ((const int4*)g_cntA)[t];
    int4 cb = ((const int4*)g_cntB)[t];
    if (ca.x + cb.x == 7) chk_list[atomicAdd(&chk_ctr, 1)] = 4 * t;
    if (ca.y + cb.y == 7) chk_list[atomicAdd(&chk_ctr, 1)] = 4 * t + 1;
    if (ca.z + cb.z == 7) chk_list[atomicAdd(&chk_ctr, 1)] = 4 * t + 2;
    if (ca.w + cb.w == 7) chk_list[atomicAdd(&chk_ctr, 1)] = 4 * t + 3;
    __syncthreads();

    // check owners cache their sorted 8-edge list in registers (rep = minimum)
    int id0 = 0, id1 = 0, id2 = 0, id3 = 0, id4 = 0, id5 = 0, id6 = 0, id7 = 0;
    if (t < NCHK) {
        int rep = chk_list[t];
        const int* pp = g_up + rep * 7;
        id0 = rep;
        id1 = pp[0]; id2 = pp[1]; id3 = pp[2]; id4 = pp[3];
        id5 = pp[4]; id6 = pp[5]; id7 = pp[6];
    }

    // ---- 5 BP iterations ------------------------------------------------------
#pragma unroll 1
    for (int it = 0; it < 5; it++) {
        // odd stage: vectorized, natural order (thread t = variable t)
        float4 ev = ((float4*)sh_even)[t];
        float vs = ev.x + ev.y + ev.z + ev.w;
        float4 od;
        od.x = tanh_acc(0.5f * (llr + vs - ev.x));
        od.y = tanh_acc(0.5f * (llr + vs - ev.y));
        od.z = tanh_acc(0.5f * (llr + vs - ev.z));
        od.w = tanh_acc(0.5f * (llr + vs - ev.w));
        ((float4*)sh_odd)[t] = od;
        __syncthreads();

        // even stage: 512 check owners gather 8, extrinsic products, scatter 8
        if (t < NCHK) {
            float a0 = zsub(sh_odd[id0]), a1 = zsub(sh_odd[id1]);
            float a2 = zsub(sh_odd[id2]), a3 = zsub(sh_odd[id3]);
            float a4 = zsub(sh_odd[id4]), a5 = zsub(sh_odd[id5]);
            float a6 = zsub(sh_odd[id6]), a7 = zsub(sh_odd[id7]);
            float p01 = a0 * a1, p23 = a2 * a3, p45 = a4 * a5, p67 = a6 * a7;
            float q03 = p01 * p23, q47 = p45 * p67;
            sh_even[id0] = atanh2(a1 * p23 * q47);
            sh_even[id1] = atanh2(a0 * p23 * q47);
            sh_even[id2] = atanh2(p01 * a3 * q47);
            sh_even[id3] = atanh2(p01 * a2 * q47);
            sh_even[id4] = atanh2(q03 * a5 * p67);
            sh_even[id5] = atanh2(q03 * a4 * p67);
            sh_even[id6] = atanh2(q03 * p45 * a7);
            sh_even[id7] = atanh2(q03 * p45 * a6);
        }
        __syncthreads();
    }

    // ---- epilogue: out[n] = sigmoid(x[n] + sum of even over var n) ------------
    float4 ev = ((float4*)sh_even)[t];
    float z = llr + ev.x + ev.y + ev.z + ev.w;
    out[t] = __fdividef(1.0f, 1.0f + __expf(-z));
}

// ---------------- launch ------------------------------------------------------
extern "C" void kernel_launch(void* const* d_in, const int* in_sizes, int n_in,
                              void* d_out, int out_size) {
    (void)in_sizes; (void)n_in; (void)out_size;
    const float*  x = (const float*)d_in[0];
    const float4* w = (const float4*)d_in[2];   // w_odd_to_even [E,E]
    float* out = (float*)d_out;

    build_peers_kernel<<<1024, 256>>>(w);   // 8192 warps, one half-row each
    decode_kernel<<<1, 1024>>>(x, out);
}